// round 5
// baseline (speedup 1.0000x reference)
#include <cuda_runtime.h>
#include <cstdint>
#include <math.h>

// IMLE sampler: out[s,b,n] = 1 iff (logits[b,n] + Gumbel(noise[s,b,n])) is in
// the row's top-k.  S=16, B=128, N=16384, k=32.
//
// v5: 4-kernel decoupled design, MUFU-free streaming phase.
//   row_sum:  per logits-row Sigma e^l -> C2[row] (deterministic reduction)
//   thresh:   fully-parallel U[i] = exp2(-C2*e^{l_i}*1.01 - 1e-6)  (u-space
//             candidate threshold; ~128 expected candidates per row)
//   collect:  barrier-free full-width stream: candidate iff u >= U[i]
//             (1 compare, no transcendentals), zero-fill out fused.
//   select:   per row: fast keys -> 2-round byte radix for kth fast key ->
//             exact double-log recompute of band survivors -> O(c^2) exact
//             rank, lowest-index tie-break (matches jax.lax.top_k).
//   fallback (unreachable on sane data): widening rescan inside select.

#define NCOLS    16384
#define NV4      (NCOLS/4)
#define LOG2N    14
#define MAXROWS  4096
#define MAXLROWS 256
#define CAP      2048
#define SURV     512
#define TARGETC  128.0f
#define DELTA    0.05f

__device__ float g_U[(size_t)MAXLROWS * NCOLS];   // u-space thresholds
__device__ float g_C2[MAXLROWS];                  // TARGETC / Sigma e^l
__device__ uint2 g_cand[(size_t)MAXROWS * CAP];   // (u bits, idx)
__device__ int   g_cnt[MAXROWS];

__device__ __forceinline__ unsigned f2k(float f) {
    unsigned b = __float_as_uint(f);
    return b ^ ((unsigned)((int)b >> 31) | 0x80000000u);
}
__device__ __forceinline__ float k2f(unsigned k) {
    unsigned b = (k & 0x80000000u) ? (k ^ 0x80000000u) : ~k;
    return __uint_as_float(b);
}
// float32 log chain, correctly rounded via double (immune to fast-math):
// t1=log(u); t3=log(-t1); p = logit - t3   (matches reference op-by-op)
__device__ __forceinline__ float exact_perturb(float u, float lg) {
    float t1 = (float)log((double)u);
    float t3 = (float)log((double)(-t1));
    return lg + (-t3);
}

// ---------------------------------------------------------------------------
__global__ __launch_bounds__(1024)
void row_sum(const float* __restrict__ logits, int nrows, int Brows)
{
    __shared__ float red[32];
    const int row = blockIdx.x, tid = threadIdx.x;
    const int lane = tid & 31, warp = tid >> 5;
    const float4* L4 = reinterpret_cast<const float4*>(logits + (size_t)row * NCOLS);

    float s = 0.f;
    #pragma unroll
    for (int c = 0; c < NV4 / 1024; ++c) {
        float4 l = __ldg(&L4[tid + c * 1024]);
        s += __expf(l.x) + __expf(l.y) + __expf(l.z) + __expf(l.w);
    }
    #pragma unroll
    for (int off = 16; off; off >>= 1) s += __shfl_xor_sync(~0u, s, off);
    if (lane == 0) red[warp] = s;
    __syncthreads();
    if (warp == 0) {
        float t = red[lane];
        #pragma unroll
        for (int off = 16; off; off >>= 1) t += __shfl_xor_sync(~0u, t, off);
        if (lane == 0) g_C2[row] = TARGETC / t;
    }
    // zero this row's share of the candidate counters
    int per = (nrows + Brows - 1) / Brows;
    for (int j = tid; j < per; j += 1024) {
        int q = row * per + j;
        if (q < nrows) g_cnt[q] = 0;
    }
}

// ---------------------------------------------------------------------------
__global__ __launch_bounds__(256)
void thresh_kernel(const float* __restrict__ logits, int total)
{
    int i = blockIdx.x * 256 + threadIdx.x;
    if (i >= total) return;
    int row = i >> LOG2N;
    const float INV_LN2 = 1.4426950408889634f;
    float G = -g_C2[row] * __expf(logits[i]) * INV_LN2;   // <= 0 (log2 space)
    float Uv = exp2f(G * 1.01f - 1e-6f);                  // widened downward
    if (!(Uv == Uv)) Uv = 0.f;                            // NaN -> always cand
    g_U[i] = Uv;
}

// ---------------------------------------------------------------------------
__global__ __launch_bounds__(512)
void collect_kernel(const float* __restrict__ noise,
                    float* __restrict__ out, int Brows)
{
    const int row = blockIdx.x, tid = threadIdx.x;
    const int lrow = row % Brows;
    const float4* n4 = reinterpret_cast<const float4*>(noise + (size_t)row * NCOLS);
    const float4* t4 = reinterpret_cast<const float4*>(g_U + (size_t)lrow * NCOLS);
    float4*       o4 = reinterpret_cast<float4*>(out + (size_t)row * NCOLS);
    const float4 z4 = make_float4(0.f, 0.f, 0.f, 0.f);

    #pragma unroll 4
    for (int c = 0; c < NV4 / 512; ++c) {
        int v = tid + c * 512;
        float4 u = __ldcs(&n4[v]);
        float4 U = __ldg(&t4[v]);
        __stcs(&o4[v], z4);
        if (u.x >= U.x) { int p = atomicAdd(&g_cnt[row], 1); if (p < CAP) g_cand[(size_t)row*CAP + p] = make_uint2(__float_as_uint(u.x), 4*v+0); }
        if (u.y >= U.y) { int p = atomicAdd(&g_cnt[row], 1); if (p < CAP) g_cand[(size_t)row*CAP + p] = make_uint2(__float_as_uint(u.y), 4*v+1); }
        if (u.z >= U.z) { int p = atomicAdd(&g_cnt[row], 1); if (p < CAP) g_cand[(size_t)row*CAP + p] = make_uint2(__float_as_uint(u.z), 4*v+2); }
        if (u.w >= U.w) { int p = atomicAdd(&g_cnt[row], 1); if (p < CAP) g_cand[(size_t)row*CAP + p] = make_uint2(__float_as_uint(u.w), 4*v+3); }
    }
}

// ---------------------------------------------------------------------------
__global__ __launch_bounds__(256)
void select_kernel(const float* __restrict__ noise,
                   const float* __restrict__ logits,
                   const int* __restrict__ kptr,
                   float* __restrict__ out, int Brows)
{
    __shared__ unsigned s_key[CAP];
    __shared__ unsigned hist[256];
    __shared__ float e_val[SURV];
    __shared__ int   e_idx[SURV];
    __shared__ int   s_misc[8];   // 0:b1 1:n1 2:b2 3:scnt 4:tot

    const int row = blockIdx.x, tid = threadIdx.x;
    const int lane = tid & 31, warp = tid >> 5;
    const int lrow = row % Brows;
    const size_t rowoff = (size_t)row * NCOLS;
    const size_t logoff = (size_t)lrow * NCOLS;

    int kk = kptr ? *kptr : 32;
    if (kk < 1) kk = 1;
    if (kk > NCOLS) kk = NCOLS;
    int cnt = g_cnt[row];

    if (cnt < kk || cnt > CAP) {
        // ---- fallback: widening rescan in log2-u space (unreachable on
        // ---- sane data; NaN-tolerant: NaN threshold => candidate)
        const float INV_LN2 = 1.4426950408889634f;
        float C2 = g_C2[lrow];
        float s = 1.0f, sHi = -1.0f;
        int chosen = 0;
        for (int it = 0; it < 64 && !chosen; ++it) {
            int c = 0;
            for (int v = tid; v < NCOLS; v += 256) {
                float t = __log2f(noise[rowoff + v]);
                float g = -C2 * __expf(logits[logoff + v]) * INV_LN2 * s - 1e-6f;
                c += (!(g == g) || t >= g) ? 1 : 0;
            }
            #pragma unroll
            for (int off = 16; off; off >>= 1) c += __shfl_xor_sync(~0u, c, off);
            if (lane == 0) hist[warp] = (unsigned)c;
            __syncthreads();
            if (tid == 0) {
                int tot = 0;
                for (int wg = 0; wg < 8; ++wg) tot += (int)hist[wg];
                s_misc[4] = tot;
            }
            __syncthreads();
            int tot = s_misc[4];
            if (tot >= kk && (sHi < 0.f || s < sHi)) sHi = s;
            if (tot >= kk && tot <= CAP) chosen = 1;
            else if (tot < kk) s *= 4.0f;
            else s *= 0.70710678f;
            __syncthreads();
        }
        if (!chosen) s = (sHi > 0.f) ? sHi : 1e30f;
        if (tid == 0) s_misc[3] = 0;
        __syncthreads();
        for (int v = tid; v < NCOLS; v += 256) {
            float uu = noise[rowoff + v];
            float t  = __log2f(uu);
            float g  = -C2 * __expf(logits[logoff + v]) * INV_LN2 * s - 1e-6f;
            if (!(g == g) || t >= g) {
                int p = atomicAdd(&s_misc[3], 1);
                if (p < CAP) g_cand[(size_t)row*CAP + p] = make_uint2(__float_as_uint(uu), v);
            }
        }
        __syncthreads();
        cnt = s_misc[3];
        if (cnt > CAP) cnt = CAP;
        if (cnt == 0) return;
    }
    if (cnt > CAP) cnt = CAP;
    if (kk > cnt) kk = cnt;

    // ---- fast keys (monotone uint encoding; NaN -> max) ----
    for (int i = tid; i < cnt; i += 256) {
        uint2 cr = g_cand[(size_t)row*CAP + i];
        float u  = __uint_as_float(cr.x);
        float lg = logits[logoff + cr.y];
        float p  = lg - __logf(-__logf(u));
        s_key[i] = (p == p) ? f2k(p) : 0xFFFFFFFFu;
    }

    // ---- radix round 1: top byte ----
    hist[tid & 255] = 0;
    __syncthreads();
    for (int i = tid; i < cnt; i += 256) atomicAdd(&hist[s_key[i] >> 24], 1u);
    __syncthreads();
    if (warp == 0) {
        int hi = 255 - lane * 8;
        unsigned part = 0;
        #pragma unroll
        for (int j = 0; j < 8; ++j) part += hist[hi - j];
        unsigned incl = part;
        #pragma unroll
        for (int off = 1; off < 32; off <<= 1) {
            unsigned v = __shfl_up_sync(~0u, incl, off);
            if (lane >= off) incl += v;
        }
        unsigned above = incl - part;
        if (above < (unsigned)kk && incl >= (unsigned)kk) {
            unsigned cum = above;
            #pragma unroll
            for (int j = 0; j < 8; ++j) {
                unsigned h = hist[hi - j];
                if (cum + h >= (unsigned)kk) { s_misc[0] = hi - j; s_misc[1] = (int)cum; break; }
                cum += h;
            }
        }
    }
    __syncthreads();
    unsigned b1 = (unsigned)s_misc[0];
    int kk2 = kk - s_misc[1];

    // ---- radix round 2: second byte among b1-prefix keys ----
    hist[tid & 255] = 0;
    __syncthreads();
    for (int i = tid; i < cnt; i += 256) {
        unsigned k = s_key[i];
        if ((k >> 24) == b1) atomicAdd(&hist[(k >> 16) & 255u], 1u);
    }
    __syncthreads();
    if (warp == 0) {
        int hi = 255 - lane * 8;
        unsigned part = 0;
        #pragma unroll
        for (int j = 0; j < 8; ++j) part += hist[hi - j];
        unsigned incl = part;
        #pragma unroll
        for (int off = 1; off < 32; off <<= 1) {
            unsigned v = __shfl_up_sync(~0u, incl, off);
            if (lane >= off) incl += v;
        }
        unsigned above = incl - part;
        if (above < (unsigned)kk2 && incl >= (unsigned)kk2) {
            unsigned cum = above;
            #pragma unroll
            for (int j = 0; j < 8; ++j) {
                unsigned h = hist[hi - j];
                if (cum + h >= (unsigned)kk2) { s_misc[2] = hi - j; break; }
                cum += h;
            }
        }
    }
    __syncthreads();
    unsigned b2 = (unsigned)s_misc[2];
    unsigned cutU = (b1 << 24) | (b2 << 16);
    float cf = k2f(cutU);
    unsigned cutAdj;
    if (!(cf == cf) || cf > 1e30f) cutAdj = cutU;   // inf/NaN region: no band
    else                           cutAdj = f2k(cf - DELTA);

    // ---- survivors: fast key >= cut - DELTA; exact recompute ----
    if (tid == 0) s_misc[3] = 0;
    __syncthreads();
    for (int i = tid; i < cnt; i += 256) {
        if (s_key[i] >= cutAdj) {
            int p = atomicAdd(&s_misc[3], 1);
            if (p < SURV) {
                uint2 cr = g_cand[(size_t)row*CAP + i];
                float u  = __uint_as_float(cr.x);
                float lg = logits[logoff + cr.y];
                e_val[p] = exact_perturb(u, lg);
                e_idx[p] = (int)cr.y;
            }
        }
    }
    __syncthreads();
    int sc = s_misc[3];
    if (sc > SURV) sc = SURV;

    // ---- exact O(sc^2) rank, lowest-index tie-break ----
    for (int i = tid; i < sc; i += 256) {
        float pi = e_val[i];
        int   ii = e_idx[i];
        int r = 0;
        for (int j = 0; j < sc; ++j) {
            float pj = e_val[j];
            r += (pj > pi) || (pj == pi && e_idx[j] < ii);
        }
        if (r < kk) out[rowoff + ii] = 1.0f;
    }
}

// ---------------------------------------------------------------------------
extern "C" void kernel_launch(void* const* d_in, const int* in_sizes, int n_in,
                              void* d_out, int out_size) {
    int iK = -1, iU = -1, iL = -1;
    for (int i = 0; i < n_in; ++i)
        if (in_sizes[i] == 1) iK = i;
    long best = -1;
    for (int i = 0; i < n_in; ++i) {
        if (i == iK) continue;
        if ((long)in_sizes[i] > best) { best = in_sizes[i]; iU = i; }
    }
    for (int i = 0; i < n_in; ++i)
        if (i != iK && i != iU) { iL = i; break; }

    const float* logits = (const float*)d_in[iL];
    const float* noise  = (const float*)d_in[iU];
    const int*   kptr   = (iK >= 0) ? (const int*)d_in[iK] : nullptr;
    float* out = (float*)d_out;

    int rows  = in_sizes[iU] / NCOLS;   // S*B = 2048
    int Brows = in_sizes[iL] / NCOLS;   // B   = 128
    if (Brows > MAXLROWS) Brows = MAXLROWS;
    if (rows  > MAXROWS)  rows  = MAXROWS;
    int nlog = Brows * NCOLS;

    row_sum<<<Brows, 1024>>>(logits, rows, Brows);
    thresh_kernel<<<(nlog + 255) / 256, 256>>>(logits, nlog);
    collect_kernel<<<rows, 512>>>(noise, out, Brows);
    select_kernel<<<rows, 256>>>(noise, logits, kptr, out, Brows);
}

// round 6
// speedup vs baseline: 1.2793x; 1.2793x over previous
#include <cuda_runtime.h>
#include <cstdint>
#include <math.h>

// IMLE sampler: out[s,b,n] = 1 iff (logits[b,n] + Gumbel(noise[s,b,n])) is in
// the row's top-k.  S=16, B=128, N=16384, k=32.
//
// v6: 2-kernel design.
//   prep: per logits-row Sigma e^l -> C2, then u-space candidate threshold
//         U[i] = exp2(-C2*e^{l_i}/ln2 * 1.01 - 1e-6)  (~128 cands/row).
//   main: one 256-thread CTA per row (8 CTAs/SM -> tails hide under other
//         CTAs' streaming):
//           stream: ldcs(noise) + ldg(U) + stcs(out=0) + compare;
//                   candidates straight to SMEM (no global round-trip)
//           tail:   fast keys -> O(c^2) rank count + atomicMin kth key ->
//                   exact double-log recompute of band survivors ->
//                   exact rank, lowest-index tie-break (jax.lax.top_k).
//   fallback (unreachable on sane data): widening rescan inside main.

#define NCOLS    16384
#define NV4      (NCOLS/4)
#define THREADS  256
#define ITERS    (NV4/THREADS)   // 16
#define MAXLROWS 256
#define CAP      1024
#define SURV     512
#define TARGETC  128.0f
#define DELTA    0.05f

__device__ float g_U[(size_t)MAXLROWS * NCOLS];
__device__ float g_C2[MAXLROWS];

__device__ __forceinline__ unsigned f2k(float f) {
    unsigned b = __float_as_uint(f);
    return b ^ ((unsigned)((int)b >> 31) | 0x80000000u);
}
__device__ __forceinline__ float k2f(unsigned k) {
    unsigned b = (k & 0x80000000u) ? (k ^ 0x80000000u) : ~k;
    return __uint_as_float(b);
}
// float32 log chain, correctly rounded via double (immune to fast-math):
// t1=log(u); t3=log(-t1); p = logit - t3   (matches reference op-by-op)
__device__ __forceinline__ float exact_perturb(float u, float lg) {
    float t1 = (float)log((double)u);
    float t3 = (float)log((double)(-t1));
    return lg + (-t3);
}

// ---------------------------------------------------------------------------
__global__ __launch_bounds__(1024)
void prep_kernel(const float* __restrict__ logits)
{
    __shared__ float red[32];
    __shared__ float s_C2;
    const int row = blockIdx.x, tid = threadIdx.x;
    const int lane = tid & 31, warp = tid >> 5;
    const float4* L4 = reinterpret_cast<const float4*>(logits + (size_t)row * NCOLS);
    float4*       U4 = reinterpret_cast<float4*>(g_U + (size_t)row * NCOLS);

    float s = 0.f;
    #pragma unroll
    for (int c = 0; c < NV4 / 1024; ++c) {
        float4 l = __ldg(&L4[tid + c * 1024]);
        s += __expf(l.x) + __expf(l.y) + __expf(l.z) + __expf(l.w);
    }
    #pragma unroll
    for (int off = 16; off; off >>= 1) s += __shfl_xor_sync(~0u, s, off);
    if (lane == 0) red[warp] = s;
    __syncthreads();
    if (warp == 0) {
        float t = red[lane];
        #pragma unroll
        for (int off = 16; off; off >>= 1) t += __shfl_xor_sync(~0u, t, off);
        if (lane == 0) { s_C2 = TARGETC / t; g_C2[row] = s_C2; }
    }
    __syncthreads();
    const float MC = -s_C2 * 1.4426950408889634f * 1.01f; // log2-space coef
    #pragma unroll
    for (int c = 0; c < NV4 / 1024; ++c) {
        float4 l = __ldg(&L4[tid + c * 1024]);
        float4 U;
        U.x = exp2f(MC * __expf(l.x) - 1e-6f);
        U.y = exp2f(MC * __expf(l.y) - 1e-6f);
        U.z = exp2f(MC * __expf(l.z) - 1e-6f);
        U.w = exp2f(MC * __expf(l.w) - 1e-6f);
        if (!(U.x == U.x)) U.x = 0.f;   // NaN -> always candidate
        if (!(U.y == U.y)) U.y = 0.f;
        if (!(U.z == U.z)) U.z = 0.f;
        if (!(U.w == U.w)) U.w = 0.f;
        U4[tid + c * 1024] = U;
    }
}

// ---------------------------------------------------------------------------
__global__ __launch_bounds__(THREADS, 8)
void main_kernel(const float* __restrict__ noise,
                 const float* __restrict__ logits,
                 const int* __restrict__ kptr,
                 float* __restrict__ out, int Brows)
{
    __shared__ unsigned s_cu[CAP];      // candidate u bits
    __shared__ int      s_ci[CAP];      // candidate index in row
    __shared__ unsigned s_key[CAP];     // fast perturbed-logit keys
    __shared__ float    e_val[SURV];
    __shared__ int      e_idx[SURV];
    __shared__ int      s_cnt, s_scnt, s_tot;
    __shared__ unsigned s_kth;

    const int row = blockIdx.x, tid = threadIdx.x;
    const int lane = tid & 31, warp = tid >> 5;
    const int lrow = row % Brows;
    const size_t rowoff = (size_t)row * NCOLS;
    const size_t logoff = (size_t)lrow * NCOLS;

    if (tid == 0) { s_cnt = 0; s_scnt = 0; s_kth = 0xFFFFFFFFu; }
    __syncthreads();

    int kk = kptr ? __ldg(kptr) : 32;
    if (kk < 1) kk = 1;
    if (kk > NCOLS) kk = NCOLS;

    // ---- Phase A: barrier-free stream (1 cmp/elem, no transcendentals) ----
    {
        const float4* n4 = reinterpret_cast<const float4*>(noise + rowoff);
        const float4* t4 = reinterpret_cast<const float4*>(g_U + (size_t)lrow * NCOLS);
        float4*       o4 = reinterpret_cast<float4*>(out + rowoff);
        const float4 z4 = make_float4(0.f, 0.f, 0.f, 0.f);
        #pragma unroll 4
        for (int c = 0; c < ITERS; ++c) {
            int v = tid + c * THREADS;
            float4 u = __ldcs(&n4[v]);
            float4 U = __ldg(&t4[v]);
            __stcs(&o4[v], z4);
            if (u.x >= U.x) { int p = atomicAdd(&s_cnt, 1); if (p < CAP) { s_cu[p] = __float_as_uint(u.x); s_ci[p] = 4*v+0; } }
            if (u.y >= U.y) { int p = atomicAdd(&s_cnt, 1); if (p < CAP) { s_cu[p] = __float_as_uint(u.y); s_ci[p] = 4*v+1; } }
            if (u.z >= U.z) { int p = atomicAdd(&s_cnt, 1); if (p < CAP) { s_cu[p] = __float_as_uint(u.z); s_ci[p] = 4*v+2; } }
            if (u.w >= U.w) { int p = atomicAdd(&s_cnt, 1); if (p < CAP) { s_cu[p] = __float_as_uint(u.w); s_ci[p] = 4*v+3; } }
        }
    }
    __syncthreads();
    int cnt = s_cnt;

    // ---- Fallback: widening rescan (unreachable on sane data) ----
    if (cnt < kk || cnt > CAP) {
        const float INV_LN2 = 1.4426950408889634f;
        float C2 = g_C2[lrow];
        float s = 1.0f, sHi = -1.0f;
        int chosen = 0;
        for (int it = 0; it < 64 && !chosen; ++it) {
            int c = 0;
            for (int v = tid; v < NCOLS; v += THREADS) {
                float t = __log2f(noise[rowoff + v]);
                float g = -C2 * __expf(logits[logoff + v]) * INV_LN2 * s - 1e-6f;
                c += (!(g == g) || t >= g) ? 1 : 0;
            }
            #pragma unroll
            for (int off = 16; off; off >>= 1) c += __shfl_xor_sync(~0u, c, off);
            if (lane == 0) s_key[warp] = (unsigned)c;   // reuse as scratch
            __syncthreads();
            if (tid == 0) {
                int tot = 0;
                for (int wg = 0; wg < THREADS / 32; ++wg) tot += (int)s_key[wg];
                s_tot = tot;
            }
            __syncthreads();
            int tot = s_tot;
            if (tot >= kk && (sHi < 0.f || s < sHi)) sHi = s;
            if (tot >= kk && tot <= CAP) chosen = 1;
            else if (tot < kk) s *= 4.0f;
            else s *= 0.70710678f;
            __syncthreads();
        }
        if (!chosen) s = (sHi > 0.f) ? sHi : 1e30f;
        if (tid == 0) s_cnt = 0;
        __syncthreads();
        for (int v = tid; v < NCOLS; v += THREADS) {
            float uu = noise[rowoff + v];
            float t  = __log2f(uu);
            float g  = -C2 * __expf(logits[logoff + v]) * INV_LN2 * s - 1e-6f;
            if (!(g == g) || t >= g) {
                int p = atomicAdd(&s_cnt, 1);
                if (p < CAP) { s_cu[p] = __float_as_uint(uu); s_ci[p] = v; }
            }
        }
        __syncthreads();
        cnt = s_cnt;
        if (cnt > CAP) cnt = CAP;
        if (cnt == 0) return;
    }
    if (cnt > CAP) cnt = CAP;
    if (kk > cnt) kk = cnt;

    // ---- Phase B: fast keys (monotone uint; NaN -> max) ----
    for (int i = tid; i < cnt; i += THREADS) {
        float u  = __uint_as_float(s_cu[i]);
        float lg = __ldg(&logits[logoff + s_ci[i]]);
        float p  = lg - __logf(-__logf(u));
        s_key[i] = (p == p) ? f2k(p) : 0xFFFFFFFFu;
    }
    __syncthreads();

    // ---- Phase C: O(c^2) rank count; kth fast key via atomicMin ----
    for (int i = tid; i < cnt; i += THREADS) {
        unsigned ki = s_key[i];
        int r = 0;
        for (int j = 0; j < cnt; ++j) r += (s_key[j] > ki);
        if (r < kk) atomicMin(&s_kth, ki);
    }
    __syncthreads();

    unsigned kth = s_kth;
    float kf = k2f(kth);
    unsigned cut = (kf == kf && kf < 1e30f && kf > -1e30f)
                   ? f2k(kf - DELTA) : kth;

    // ---- Phase D: band survivors -> exact recompute ----
    for (int i = tid; i < cnt; i += THREADS) {
        if (s_key[i] >= cut) {
            int p = atomicAdd(&s_scnt, 1);
            if (p < SURV) {
                float u  = __uint_as_float(s_cu[i]);
                float lg = __ldg(&logits[logoff + s_ci[i]]);
                e_val[p] = exact_perturb(u, lg);
                e_idx[p] = s_ci[i];
            }
        }
    }
    __syncthreads();
    int sc = s_scnt;
    if (sc > SURV) sc = SURV;

    // ---- Phase E: exact O(sc^2) rank, lowest-index tie-break ----
    for (int i = tid; i < sc; i += THREADS) {
        float pi = e_val[i];
        int   ii = e_idx[i];
        int r = 0;
        for (int j = 0; j < sc; ++j) {
            float pj = e_val[j];
            r += (pj > pi) || (pj == pi && e_idx[j] < ii);
        }
        if (r < kk) out[rowoff + ii] = 1.0f;
    }
}

// ---------------------------------------------------------------------------
extern "C" void kernel_launch(void* const* d_in, const int* in_sizes, int n_in,
                              void* d_out, int out_size) {
    int iK = -1, iU = -1, iL = -1;
    for (int i = 0; i < n_in; ++i)
        if (in_sizes[i] == 1) iK = i;
    long best = -1;
    for (int i = 0; i < n_in; ++i) {
        if (i == iK) continue;
        if ((long)in_sizes[i] > best) { best = in_sizes[i]; iU = i; }
    }
    for (int i = 0; i < n_in; ++i)
        if (i != iK && i != iU) { iL = i; break; }

    const float* logits = (const float*)d_in[iL];
    const float* noise  = (const float*)d_in[iU];
    const int*   kptr   = (iK >= 0) ? (const int*)d_in[iK] : nullptr;
    float* out = (float*)d_out;

    int rows  = in_sizes[iU] / NCOLS;   // S*B = 2048
    int Brows = in_sizes[iL] / NCOLS;   // B   = 128
    if (Brows > MAXLROWS) Brows = MAXLROWS;

    prep_kernel<<<Brows, 1024>>>(logits);
    main_kernel<<<rows, THREADS>>>(noise, logits, kptr, out, Brows);
}

// round 7
// speedup vs baseline: 1.3869x; 1.0841x over previous
#include <cuda_runtime.h>
#include <cstdint>
#include <math.h>

// IMLE sampler: out[s,b,n] = 1 iff (logits[b,n] + Gumbel(noise[s,b,n])) is in
// the row's top-k.  S=16, B=128, N=16384, k=32.
//
// v7 = v6 + streaming-rate fixes:
//   - launch_bounds(256,6): 42 regs/thread (was 32) -> real MLP
//   - 2 float4-pairs of loads batched per loop step (4 LDG.128 in flight)
//   - branch-free compares + single rare branch per float4
// prep: row Sigma e^l -> C2 -> u-space threshold U[i] (~128 cands/row).
// main: per-row CTA: barrier-free stream (1 cmp/elem) -> smem candidates ->
//       fast keys -> O(c^2) kth -> exact double-log band recompute ->
//       exact rank, lowest-index tie-break (matches jax.lax.top_k).

#define NCOLS    16384
#define NV4      (NCOLS/4)
#define THREADS  256
#define ITERS    (NV4/THREADS)   // 16
#define MAXLROWS 256
#define CAP      1024
#define SURV     512
#define TARGETC  128.0f
#define DELTA    0.05f

__device__ float g_U[(size_t)MAXLROWS * NCOLS];
__device__ float g_C2[MAXLROWS];

__device__ __forceinline__ unsigned f2k(float f) {
    unsigned b = __float_as_uint(f);
    return b ^ ((unsigned)((int)b >> 31) | 0x80000000u);
}
__device__ __forceinline__ float k2f(unsigned k) {
    unsigned b = (k & 0x80000000u) ? (k ^ 0x80000000u) : ~k;
    return __uint_as_float(b);
}
// float32 log chain, correctly rounded via double (immune to fast-math):
// t1=log(u); t3=log(-t1); p = logit - t3   (matches reference op-by-op)
__device__ __forceinline__ float exact_perturb(float u, float lg) {
    float t1 = (float)log((double)u);
    float t3 = (float)log((double)(-t1));
    return lg + (-t3);
}

// ---------------------------------------------------------------------------
__global__ __launch_bounds__(1024)
void prep_kernel(const float* __restrict__ logits)
{
    __shared__ float red[32];
    __shared__ float s_C2;
    const int row = blockIdx.x, tid = threadIdx.x;
    const int lane = tid & 31, warp = tid >> 5;
    const float4* L4 = reinterpret_cast<const float4*>(logits + (size_t)row * NCOLS);
    float4*       U4 = reinterpret_cast<float4*>(g_U + (size_t)row * NCOLS);

    float s = 0.f;
    #pragma unroll
    for (int c = 0; c < NV4 / 1024; ++c) {
        float4 l = __ldg(&L4[tid + c * 1024]);
        s += __expf(l.x) + __expf(l.y) + __expf(l.z) + __expf(l.w);
    }
    #pragma unroll
    for (int off = 16; off; off >>= 1) s += __shfl_xor_sync(~0u, s, off);
    if (lane == 0) red[warp] = s;
    __syncthreads();
    if (warp == 0) {
        float t = red[lane];
        #pragma unroll
        for (int off = 16; off; off >>= 1) t += __shfl_xor_sync(~0u, t, off);
        if (lane == 0) { s_C2 = TARGETC / t; g_C2[row] = s_C2; }
    }
    __syncthreads();
    const float MC = -s_C2 * 1.4426950408889634f * 1.01f; // log2-space coef
    #pragma unroll
    for (int c = 0; c < NV4 / 1024; ++c) {
        float4 l = __ldg(&L4[tid + c * 1024]);
        float4 U;
        U.x = exp2f(MC * __expf(l.x) - 1e-6f);
        U.y = exp2f(MC * __expf(l.y) - 1e-6f);
        U.z = exp2f(MC * __expf(l.z) - 1e-6f);
        U.w = exp2f(MC * __expf(l.w) - 1e-6f);
        if (!(U.x == U.x)) U.x = 0.f;   // NaN -> always candidate
        if (!(U.y == U.y)) U.y = 0.f;
        if (!(U.z == U.z)) U.z = 0.f;
        if (!(U.w == U.w)) U.w = 0.f;
        U4[tid + c * 1024] = U;
    }
}

// ---------------------------------------------------------------------------
__device__ __forceinline__ void cand4(float4 u, float4 U, int v,
                                      int* s_cnt, unsigned* s_cu, int* s_ci)
{
    bool b0 = u.x >= U.x, b1 = u.y >= U.y, b2 = u.z >= U.z, b3 = u.w >= U.w;
    if (b0 | b1 | b2 | b3) {                       // rare (~2.8% of float4s)
        if (b0) { int p = atomicAdd(s_cnt, 1); if (p < CAP) { s_cu[p] = __float_as_uint(u.x); s_ci[p] = 4*v+0; } }
        if (b1) { int p = atomicAdd(s_cnt, 1); if (p < CAP) { s_cu[p] = __float_as_uint(u.y); s_ci[p] = 4*v+1; } }
        if (b2) { int p = atomicAdd(s_cnt, 1); if (p < CAP) { s_cu[p] = __float_as_uint(u.z); s_ci[p] = 4*v+2; } }
        if (b3) { int p = atomicAdd(s_cnt, 1); if (p < CAP) { s_cu[p] = __float_as_uint(u.w); s_ci[p] = 4*v+3; } }
    }
}

__global__ __launch_bounds__(THREADS, 6)
void main_kernel(const float* __restrict__ noise,
                 const float* __restrict__ logits,
                 const int* __restrict__ kptr,
                 float* __restrict__ out, int Brows)
{
    __shared__ unsigned s_cu[CAP];      // candidate u bits
    __shared__ int      s_ci[CAP];      // candidate index in row
    __shared__ unsigned s_key[CAP];     // fast perturbed-logit keys
    __shared__ float    e_val[SURV];
    __shared__ int      e_idx[SURV];
    __shared__ int      s_cnt, s_scnt, s_tot;
    __shared__ unsigned s_kth;

    const int row = blockIdx.x, tid = threadIdx.x;
    const int lane = tid & 31, warp = tid >> 5;
    const int lrow = row % Brows;
    const size_t rowoff = (size_t)row * NCOLS;
    const size_t logoff = (size_t)lrow * NCOLS;

    if (tid == 0) { s_cnt = 0; s_scnt = 0; s_kth = 0xFFFFFFFFu; }
    __syncthreads();

    int kk = kptr ? __ldg(kptr) : 32;
    if (kk < 1) kk = 1;
    if (kk > NCOLS) kk = NCOLS;

    // ---- Phase A: barrier-free stream; 4 LDG.128 batched per step ----
    {
        const float4* n4 = reinterpret_cast<const float4*>(noise + rowoff);
        const float4* t4 = reinterpret_cast<const float4*>(g_U + (size_t)lrow * NCOLS);
        float4*       o4 = reinterpret_cast<float4*>(out + rowoff);
        const float4 z4 = make_float4(0.f, 0.f, 0.f, 0.f);
        #pragma unroll
        for (int c = 0; c < ITERS / 2; ++c) {
            int v0 = tid + (2*c) * THREADS;
            int v1 = v0 + THREADS;
            float4 u0 = __ldcs(&n4[v0]);
            float4 U0 = __ldg(&t4[v0]);
            float4 u1 = __ldcs(&n4[v1]);
            float4 U1 = __ldg(&t4[v1]);
            __stcs(&o4[v0], z4);
            __stcs(&o4[v1], z4);
            cand4(u0, U0, v0, &s_cnt, s_cu, s_ci);
            cand4(u1, U1, v1, &s_cnt, s_cu, s_ci);
        }
    }
    __syncthreads();
    int cnt = s_cnt;

    // ---- Fallback: widening rescan (unreachable on sane data) ----
    if (cnt < kk || cnt > CAP) {
        const float INV_LN2 = 1.4426950408889634f;
        float C2 = g_C2[lrow];
        float s = 1.0f, sHi = -1.0f;
        int chosen = 0;
        for (int it = 0; it < 64 && !chosen; ++it) {
            int c = 0;
            for (int v = tid; v < NCOLS; v += THREADS) {
                float t = __log2f(noise[rowoff + v]);
                float g = -C2 * __expf(logits[logoff + v]) * INV_LN2 * s - 1e-6f;
                c += (!(g == g) || t >= g) ? 1 : 0;
            }
            #pragma unroll
            for (int off = 16; off; off >>= 1) c += __shfl_xor_sync(~0u, c, off);
            if (lane == 0) s_key[warp] = (unsigned)c;   // scratch
            __syncthreads();
            if (tid == 0) {
                int tot = 0;
                for (int wg = 0; wg < THREADS / 32; ++wg) tot += (int)s_key[wg];
                s_tot = tot;
            }
            __syncthreads();
            int tot = s_tot;
            if (tot >= kk && (sHi < 0.f || s < sHi)) sHi = s;
            if (tot >= kk && tot <= CAP) chosen = 1;
            else if (tot < kk) s *= 4.0f;
            else s *= 0.70710678f;
            __syncthreads();
        }
        if (!chosen) s = (sHi > 0.f) ? sHi : 1e30f;
        if (tid == 0) s_cnt = 0;
        __syncthreads();
        for (int v = tid; v < NCOLS; v += THREADS) {
            float uu = noise[rowoff + v];
            float t  = __log2f(uu);
            float g  = -C2 * __expf(logits[logoff + v]) * INV_LN2 * s - 1e-6f;
            if (!(g == g) || t >= g) {
                int p = atomicAdd(&s_cnt, 1);
                if (p < CAP) { s_cu[p] = __float_as_uint(uu); s_ci[p] = v; }
            }
        }
        __syncthreads();
        cnt = s_cnt;
        if (cnt > CAP) cnt = CAP;
        if (cnt == 0) return;
    }
    if (cnt > CAP) cnt = CAP;
    if (kk > cnt) kk = cnt;

    // ---- Phase B: fast keys (monotone uint; NaN -> max) ----
    for (int i = tid; i < cnt; i += THREADS) {
        float u  = __uint_as_float(s_cu[i]);
        float lg = __ldg(&logits[logoff + s_ci[i]]);
        float p  = lg - __logf(-__logf(u));
        s_key[i] = (p == p) ? f2k(p) : 0xFFFFFFFFu;
    }
    __syncthreads();

    // ---- Phase C: O(c^2) rank count; kth fast key via atomicMin ----
    for (int i = tid; i < cnt; i += THREADS) {
        unsigned ki = s_key[i];
        int r = 0;
        for (int j = 0; j < cnt; ++j) r += (s_key[j] > ki);
        if (r < kk) atomicMin(&s_kth, ki);
    }
    __syncthreads();

    unsigned kth = s_kth;
    float kf = k2f(kth);
    unsigned cut = (kf == kf && kf < 1e30f && kf > -1e30f)
                   ? f2k(kf - DELTA) : kth;

    // ---- Phase D: band survivors -> exact recompute ----
    for (int i = tid; i < cnt; i += THREADS) {
        if (s_key[i] >= cut) {
            int p = atomicAdd(&s_scnt, 1);
            if (p < SURV) {
                float u  = __uint_as_float(s_cu[i]);
                float lg = __ldg(&logits[logoff + s_ci[i]]);
                e_val[p] = exact_perturb(u, lg);
                e_idx[p] = s_ci[i];
            }
        }
    }
    __syncthreads();
    int sc = s_scnt;
    if (sc > SURV) sc = SURV;

    // ---- Phase E: exact O(sc^2) rank, lowest-index tie-break ----
    for (int i = tid; i < sc; i += THREADS) {
        float pi = e_val[i];
        int   ii = e_idx[i];
        int r = 0;
        for (int j = 0; j < sc; ++j) {
            float pj = e_val[j];
            r += (pj > pi) || (pj == pi && e_idx[j] < ii);
        }
        if (r < kk) out[rowoff + ii] = 1.0f;
    }
}

// ---------------------------------------------------------------------------
extern "C" void kernel_launch(void* const* d_in, const int* in_sizes, int n_in,
                              void* d_out, int out_size) {
    int iK = -1, iU = -1, iL = -1;
    for (int i = 0; i < n_in; ++i)
        if (in_sizes[i] == 1) iK = i;
    long best = -1;
    for (int i = 0; i < n_in; ++i) {
        if (i == iK) continue;
        if ((long)in_sizes[i] > best) { best = in_sizes[i]; iU = i; }
    }
    for (int i = 0; i < n_in; ++i)
        if (i != iK && i != iU) { iL = i; break; }

    const float* logits = (const float*)d_in[iL];
    const float* noise  = (const float*)d_in[iU];
    const int*   kptr   = (iK >= 0) ? (const int*)d_in[iK] : nullptr;
    float* out = (float*)d_out;

    int rows  = in_sizes[iU] / NCOLS;   // S*B = 2048
    int Brows = in_sizes[iL] / NCOLS;   // B   = 128
    if (Brows > MAXLROWS) Brows = MAXLROWS;

    prep_kernel<<<Brows, 1024>>>(logits);
    main_kernel<<<rows, THREADS>>>(noise, logits, kptr, out, Brows);
}